// round 6
// baseline (speedup 1.0000x reference)
#include <cuda_runtime.h>
#include <cstdint>

#define SLOPE 0.2f
#define THREADS 256

typedef unsigned long long u64;

// ---------------- packed f32x2 helpers (Blackwell FFMA2 path) ----------------
__device__ __forceinline__ u64 fma2(u64 a, u64 b, u64 c) {
    u64 d;
    asm("fma.rn.f32x2 %0, %1, %2, %3;" : "=l"(d) : "l"(a), "l"(b), "l"(c));
    return d;
}
__device__ __forceinline__ u64 dup2(float x) {
    u64 d;
    asm("mov.b64 %0, {%1, %1};" : "=l"(d) : "f"(x));
    return d;
}
__device__ __forceinline__ float2 unpack2(u64 v) {
    float2 r;
    asm("mov.b64 {%0, %1}, %2;" : "=f"(r.x), "=f"(r.y) : "l"(v));
    return r;
}

// ---------------- shared memory layout (float offsets) ----------------
// Weights transposed: Wt[k*128 + h] = W[h][k]
#define OFF_W1   0                       // [65][128]
#define OFF_W2   (65*128)                // [128][128]
#define OFF_W3   (OFF_W2 + 128*128)      // [128][128]
#define OFF_B1   (OFF_W3 + 128*128)
#define OFF_B2   (OFF_B1 + 128)
#define OFF_B3   (OFF_B2 + 128)
#define OFF_W4   (OFF_B3 + 128)
#define OFF_BA0  (OFF_W4 + 128)          // [128][32] activation ping
#define OFF_BD0  (OFF_BA0 + 128*32)      // [128][32] deriv ping
#define OFF_BA1  (OFF_BD0 + 128*32)      // [128][32] activation pong (aliases x-tile & reduce scratch)
#define OFF_BD1  (OFF_BA1 + 128*32)      // [128][32] deriv pong
#define SMEM_FLOATS (OFF_BD1 + 128*32)   // 57,984 floats = 231,936 B  (< 232,448 cap)

// deterministic cross-d logdet partials: scratch[d][n]
__device__ float g_scratch[64 * 4096];

// Fused forward + derivative GEMM over one layer.
// m-pair packing: each thread owns 8 samples (m0..m0+7, packed as 4 f32x2 pairs)
// x 2 hidden units (h0, h0+1). Packed A/D operands come straight out of LDS.128
// with NO broadcast MOVs; only the 2 weight scalars per k need dup2.
__device__ __forceinline__ void gemm_fused(
    float* sm, int offAin, int offDin, int offW, int offB,
    int offAout, int offDout, int m0, int h0)
{
    u64 accA[2][4], accD[2][4];
#pragma unroll
    for (int i = 0; i < 2; i++)
#pragma unroll
        for (int j = 0; j < 4; j++) { accA[i][j] = 0ull; accD[i][j] = 0ull; }

    const float* Ain = sm + offAin;
    const float* Din = sm + offDin;
    const float* Wt  = sm + offW;

#pragma unroll 8
    for (int k = 0; k < 128; k++) {
        ulonglong2 a01 = *(const ulonglong2*)(Ain + k * 32 + m0);
        ulonglong2 a23 = *(const ulonglong2*)(Ain + k * 32 + m0 + 4);
        ulonglong2 d01 = *(const ulonglong2*)(Din + k * 32 + m0);
        ulonglong2 d23 = *(const ulonglong2*)(Din + k * 32 + m0 + 4);
        float2 wf = *(const float2*)(Wt + k * 128 + h0);
        u64 w0 = dup2(wf.x);
        u64 w1 = dup2(wf.y);
        u64 a[4]  = { a01.x, a01.y, a23.x, a23.y };
        u64 dd[4] = { d01.x, d01.y, d23.x, d23.y };
#pragma unroll
        for (int mp = 0; mp < 4; mp++) {
            accA[0][mp] = fma2(a[mp],  w0, accA[0][mp]);
            accA[1][mp] = fma2(a[mp],  w1, accA[1][mp]);
            accD[0][mp] = fma2(dd[mp], w0, accD[0][mp]);
            accD[1][mp] = fma2(dd[mp], w1, accD[1][mp]);
        }
    }

    float* Aout = sm + offAout;
    float* Dout = sm + offDout;
#pragma unroll
    for (int hp = 0; hp < 2; hp++) {
        const int h = h0 + hp;
        const float bias = sm[offB + h];
        float oa[8], od[8];
#pragma unroll
        for (int mp = 0; mp < 4; mp++) {
            float2 pa = unpack2(accA[hp][mp]);
            float2 pd = unpack2(accD[hp][mp]);
            float p0 = pa.x + bias; float s0 = (p0 > 0.f) ? 1.f : SLOPE;
            oa[2 * mp]     = p0 * s0;  od[2 * mp]     = s0 * pd.x;
            float p1 = pa.y + bias; float s1 = (p1 > 0.f) ? 1.f : SLOPE;
            oa[2 * mp + 1] = p1 * s1;  od[2 * mp + 1] = s1 * pd.y;
        }
        *(float4*)(Aout + h * 32 + m0)     = make_float4(oa[0], oa[1], oa[2], oa[3]);
        *(float4*)(Aout + h * 32 + m0 + 4) = make_float4(oa[4], oa[5], oa[6], oa[7]);
        *(float4*)(Dout + h * 32 + m0)     = make_float4(od[0], od[1], od[2], od[3]);
        *(float4*)(Dout + h * 32 + m0 + 4) = make_float4(od[4], od[5], od[6], od[7]);
    }
}

__global__ void __launch_bounds__(THREADS, 1)
npt_kernel(const float* __restrict__ x,
           const float* __restrict__ W1, const float* __restrict__ b1,
           const float* __restrict__ W2, const float* __restrict__ b2,
           const float* __restrict__ W3, const float* __restrict__ b3,
           const float* __restrict__ W4, const float* __restrict__ b4,
           float* __restrict__ out_res)
{
    extern __shared__ float sm[];
    const int tid  = threadIdx.x;
    const int d    = blockIdx.x >> 1;   // latent index
    const int half = blockIdx.x & 1;    // sample half [0..2048) / [2048..4096)

    // -------- load + transpose weights for this latent into SMEM (256 threads) --------
    {
        const int h  = tid & 127;  // hidden unit
        const int hf = tid >> 7;   // k-range half (0/1)

        // W1: hf=0 -> k in [0,33), hf=1 -> k in [33,65)
        const float* w1r = W1 + (size_t)(d * 128 + h) * 65;
        const int kbeg = hf ? 33 : 0;
        const int kend = hf ? 65 : 33;
        for (int k = kbeg; k < kend; k++) sm[OFF_W1 + k * 128 + h] = w1r[k];

        // W2/W3: hf=0 -> k in [0,64), hf=1 -> k in [64,128)
        const float* w2r = W2 + (size_t)(d * 128 + h) * 128;
        const float* w3r = W3 + (size_t)(d * 128 + h) * 128;
        const int k0 = hf * 64;
#pragma unroll
        for (int kk = 0; kk < 64; kk += 4) {
            const int k4 = k0 + kk;
            float4 v2 = *(const float4*)(w2r + k4);
            sm[OFF_W2 + (k4 + 0) * 128 + h] = v2.x;
            sm[OFF_W2 + (k4 + 1) * 128 + h] = v2.y;
            sm[OFF_W2 + (k4 + 2) * 128 + h] = v2.z;
            sm[OFF_W2 + (k4 + 3) * 128 + h] = v2.w;
            float4 v3 = *(const float4*)(w3r + k4);
            sm[OFF_W3 + (k4 + 0) * 128 + h] = v3.x;
            sm[OFF_W3 + (k4 + 1) * 128 + h] = v3.y;
            sm[OFF_W3 + (k4 + 2) * 128 + h] = v3.z;
            sm[OFF_W3 + (k4 + 3) * 128 + h] = v3.w;
        }
        if (hf == 0) {
            sm[OFF_B1 + h] = b1[d * 128 + h];
            sm[OFF_B2 + h] = b2[d * 128 + h];
            sm[OFF_B3 + h] = b3[d * 128 + h];
            sm[OFF_W4 + h] = W4[d * 128 + h];
        }
    }
    const float b4d = b4[d];
    __syncthreads();

    // m-pair mapping: 4 m-groups x 64 h-groups
    const int m0 = (tid & 3) * 8;   // 8 samples per thread
    const int h0 = (tid >> 2) * 2;  // 2 hidden units per thread

    for (int tile = 0; tile < 64; tile++) {
        const int n0 = half * 2048 + tile * 32;
        const int b  = n0 >> 8;     // batch
        const int t0 = n0 & 255;    // time within batch

        // -------- stage input tile xl[k][m] (k<64: x[b,t,k]; k==64: x[b,t+1,d]) --------
        {
            float* xl = sm + OFF_BA1;  // BA1 is dead here; aliased as x-tile
            const int m = tid >> 3, part = tid & 7;   // 32 m rows x 8 threads x 8 floats
            const float* xr = x + ((size_t)(b * 257 + t0 + m)) * 64 + part * 8;
#pragma unroll
            for (int i = 0; i < 8; i += 4) {
                float4 v = *(const float4*)(xr + i);
                const int k = part * 8 + i;
                xl[(k + 0) * 32 + m] = v.x;
                xl[(k + 1) * 32 + m] = v.y;
                xl[(k + 2) * 32 + m] = v.z;
                xl[(k + 3) * 32 + m] = v.w;
            }
            if (tid < 32)
                xl[64 * 32 + tid] = x[((size_t)(b * 257 + t0 + tid + 1)) * 64 + d];
        }
        __syncthreads();

        // -------- Layer 1 (K=65, forward only) -> BA0 (a1), BD0 (d1 = s1 * W1[:,64]) --------
        {
            u64 accA[2][4];
#pragma unroll
            for (int i = 0; i < 2; i++)
#pragma unroll
                for (int j = 0; j < 4; j++) accA[i][j] = 0ull;

            const float* xl = sm + OFF_BA1;
            const float* Wt = sm + OFF_W1;
#pragma unroll 5
            for (int k = 0; k < 65; k++) {
                ulonglong2 a01 = *(const ulonglong2*)(xl + k * 32 + m0);
                ulonglong2 a23 = *(const ulonglong2*)(xl + k * 32 + m0 + 4);
                float2 wf = *(const float2*)(Wt + k * 128 + h0);
                u64 w0 = dup2(wf.x);
                u64 w1 = dup2(wf.y);
                u64 a[4] = { a01.x, a01.y, a23.x, a23.y };
#pragma unroll
                for (int mp = 0; mp < 4; mp++) {
                    accA[0][mp] = fma2(a[mp], w0, accA[0][mp]);
                    accA[1][mp] = fma2(a[mp], w1, accA[1][mp]);
                }
            }
            float* Aout = sm + OFF_BA0;
            float* Dout = sm + OFF_BD0;
#pragma unroll
            for (int hp = 0; hp < 2; hp++) {
                const int h = h0 + hp;
                const float bias = sm[OFF_B1 + h];
                const float wc   = sm[OFF_W1 + 64 * 128 + h];
                float oa[8], od[8];
#pragma unroll
                for (int mp = 0; mp < 4; mp++) {
                    float2 pa = unpack2(accA[hp][mp]);
                    float p0 = pa.x + bias; float s0 = (p0 > 0.f) ? 1.f : SLOPE;
                    oa[2 * mp]     = p0 * s0;  od[2 * mp]     = s0 * wc;
                    float p1 = pa.y + bias; float s1 = (p1 > 0.f) ? 1.f : SLOPE;
                    oa[2 * mp + 1] = p1 * s1;  od[2 * mp + 1] = s1 * wc;
                }
                *(float4*)(Aout + h * 32 + m0)     = make_float4(oa[0], oa[1], oa[2], oa[3]);
                *(float4*)(Aout + h * 32 + m0 + 4) = make_float4(oa[4], oa[5], oa[6], oa[7]);
                *(float4*)(Dout + h * 32 + m0)     = make_float4(od[0], od[1], od[2], od[3]);
                *(float4*)(Dout + h * 32 + m0 + 4) = make_float4(od[4], od[5], od[6], od[7]);
            }
        }
        __syncthreads();

        // -------- Layer 2 fused fwd+deriv: BA0/BD0 -> BA1/BD1 --------
        gemm_fused(sm, OFF_BA0, OFF_BD0, OFF_W2, OFF_B2, OFF_BA1, OFF_BD1, m0, h0);
        __syncthreads();

        // -------- Layer 3 fused fwd+deriv: BA1/BD1 -> BA0/BD0 --------
        gemm_fused(sm, OFF_BA1, OFF_BD1, OFF_W3, OFF_B3, OFF_BA0, OFF_BD0, m0, h0);
        __syncthreads();

        // -------- Layer 4 reductions: residual + log|deriv| --------
        {
            float* red = sm + OFF_BA1;  // scratch aliases BA1 (dead)
            const int m = tid & 31, q = tid >> 5;   // 8 groups x 16 h each
            const float* A3 = sm + OFF_BA0;
            const float* D3 = sm + OFF_BD0;
            float pa = 0.f, pd = 0.f;
#pragma unroll
            for (int hh = 0; hh < 16; hh++) {
                const int h = q * 16 + hh;
                const float w = sm[OFF_W4 + h];
                pa += A3[h * 32 + m] * w;
                pd += D3[h * 32 + m] * w;
            }
            red[q * 32 + m]       = pa;
            red[256 + q * 32 + m] = pd;
            __syncthreads();
            if (tid < 32) {
                const int n = n0 + tid;
                float res = b4d;
                float dv  = 0.f;
#pragma unroll
                for (int q2 = 0; q2 < 8; q2++) {
                    res += red[q2 * 32 + tid];
                    dv  += red[256 + q2 * 32 + tid];
                }
                out_res[(size_t)n * 64 + d] = res;
                g_scratch[d * 4096 + n] = logf(fabsf(dv) + 1e-8f);
            }
        }
        __syncthreads();
    }
}

// deterministic sum over latents: out_logdet[n] = sum_d scratch[d][n]
__global__ void reduce_logdet_kernel(float* __restrict__ out_ld)
{
    const int n = blockIdx.x * blockDim.x + threadIdx.x;
    if (n < 4096) {
        float s = 0.f;
#pragma unroll
        for (int d = 0; d < 64; d++) s += g_scratch[d * 4096 + n];
        out_ld[n] = s;
    }
}

extern "C" void kernel_launch(void* const* d_in, const int* in_sizes, int n_in,
                              void* d_out, int out_size)
{
    const float* x  = (const float*)d_in[0];
    const float* W1 = (const float*)d_in[1];
    const float* b1 = (const float*)d_in[2];
    const float* W2 = (const float*)d_in[3];
    const float* b2 = (const float*)d_in[4];
    const float* W3 = (const float*)d_in[5];
    const float* b3 = (const float*)d_in[6];
    const float* W4 = (const float*)d_in[7];
    const float* b4 = (const float*)d_in[8];
    (void)in_sizes; (void)n_in; (void)out_size;

    float* out_res = (float*)d_out;                  // [16,256,64]
    float* out_ld  = (float*)d_out + 16 * 256 * 64;  // [16,256]

    const size_t smem = (size_t)SMEM_FLOATS * sizeof(float);  // 231,936 B
    cudaFuncSetAttribute(npt_kernel, cudaFuncAttributeMaxDynamicSharedMemorySize, (int)smem);

    npt_kernel<<<128, THREADS, smem>>>(x, W1, b1, W2, b2, W3, b3, W4, b4, out_res);
    reduce_logdet_kernel<<<16, 256>>>(out_ld);
}

// round 8
// speedup vs baseline: 1.4638x; 1.4638x over previous
#include <cuda_runtime.h>
#include <cstdint>

#define SLOPE 0.2f
#define THREADS 128

typedef unsigned long long u64;

// ---------------- packed f32x2 helpers (Blackwell FFMA2 path) ----------------
__device__ __forceinline__ u64 fma2(u64 a, u64 b, u64 c) {
    u64 d;
    asm("fma.rn.f32x2 %0, %1, %2, %3;" : "=l"(d) : "l"(a), "l"(b), "l"(c));
    return d;
}
__device__ __forceinline__ u64 dup2(float x) {
    u64 d;
    asm("mov.b64 %0, {%1, %1};" : "=l"(d) : "f"(x));
    return d;
}
__device__ __forceinline__ float2 unpack2(u64 v) {
    float2 r;
    asm("mov.b64 {%0, %1}, %2;" : "=f"(r.x), "=f"(r.y) : "l"(v));
    return r;
}

// ---------------- shared memory layout (float offsets) ----------------
// Weights transposed: Wt[k*128 + h] = W[h][k]
#define OFF_W1   0                       // [65][128]
#define OFF_W2   (65*128)                // [128][128]
#define OFF_W3   (OFF_W2 + 128*128)      // [128][128]
#define OFF_B1   (OFF_W3 + 128*128)
#define OFF_B2   (OFF_B1 + 128)
#define OFF_B3   (OFF_B2 + 128)
#define OFF_W4   (OFF_B3 + 128)
#define OFF_BA0  (OFF_W4 + 128)          // [128][32] activation ping
#define OFF_BD0  (OFF_BA0 + 128*32)      // [128][32] deriv ping
#define OFF_BA1  (OFF_BD0 + 128*32)      // [128][32] activation pong (aliases x-tile & reduce scratch)
#define OFF_BD1  (OFF_BA1 + 128*32)      // [128][32] deriv pong
#define SMEM_FLOATS (OFF_BD1 + 128*32)   // 57,984 floats = 231,936 B  (< 232,448 cap)

// deterministic cross-d logdet partials: scratch[d][n]
__device__ float g_scratch[64 * 4096];

// Fused forward + derivative GEMM over one layer.
// Micro-tile: 8 samples (m0..m0+7, as 4 f32x2 m-pairs) x 4 hidden (h0..h0+3).
// m-pair packing: packed A/D operands come straight from LDS.128 (no MOVs);
// only 4 weight scalars per k need dup2.
// Per k: 32 fma2 + 4 dup2 + 5 LDS.128  (1.28 issues per fma2)
__device__ __forceinline__ void gemm_fused(
    float* sm, int offAin, int offDin, int offW, int offB,
    int offAout, int offDout, int m0, int h0)
{
    u64 accA[4][4], accD[4][4];   // [h][m-pair]
#pragma unroll
    for (int i = 0; i < 4; i++)
#pragma unroll
        for (int j = 0; j < 4; j++) { accA[i][j] = 0ull; accD[i][j] = 0ull; }

    const float* Ain = sm + offAin;
    const float* Din = sm + offDin;
    const float* Wt  = sm + offW;

#pragma unroll 4
    for (int k = 0; k < 128; k++) {
        ulonglong2 aA = *(const ulonglong2*)(Ain + k * 32 + m0);      // m-pairs 0,1
        ulonglong2 aB = *(const ulonglong2*)(Ain + k * 32 + m0 + 4);  // m-pairs 2,3
        ulonglong2 dA = *(const ulonglong2*)(Din + k * 32 + m0);
        ulonglong2 dB = *(const ulonglong2*)(Din + k * 32 + m0 + 4);
        float4 wf = *(const float4*)(Wt + k * 128 + h0);
        u64 w[4]  = { dup2(wf.x), dup2(wf.y), dup2(wf.z), dup2(wf.w) };
        u64 a[4]  = { aA.x, aA.y, aB.x, aB.y };
        u64 dd[4] = { dA.x, dA.y, dB.x, dB.y };
#pragma unroll
        for (int h = 0; h < 4; h++)
#pragma unroll
            for (int mp = 0; mp < 4; mp++) {
                accA[h][mp] = fma2(a[mp],  w[h], accA[h][mp]);
                accD[h][mp] = fma2(dd[mp], w[h], accD[h][mp]);
            }
    }

    float* Aout = sm + offAout;
    float* Dout = sm + offDout;
#pragma unroll
    for (int hp = 0; hp < 4; hp++) {
        const int h = h0 + hp;
        const float bias = sm[offB + h];
        float oa[8], od[8];
#pragma unroll
        for (int mp = 0; mp < 4; mp++) {
            float2 pa = unpack2(accA[hp][mp]);
            float2 pd = unpack2(accD[hp][mp]);
            float p0 = pa.x + bias; float s0 = (p0 > 0.f) ? 1.f : SLOPE;
            oa[2 * mp]     = p0 * s0;  od[2 * mp]     = s0 * pd.x;
            float p1 = pa.y + bias; float s1 = (p1 > 0.f) ? 1.f : SLOPE;
            oa[2 * mp + 1] = p1 * s1;  od[2 * mp + 1] = s1 * pd.y;
        }
        *(float4*)(Aout + h * 32 + m0)     = make_float4(oa[0], oa[1], oa[2], oa[3]);
        *(float4*)(Aout + h * 32 + m0 + 4) = make_float4(oa[4], oa[5], oa[6], oa[7]);
        *(float4*)(Dout + h * 32 + m0)     = make_float4(od[0], od[1], od[2], od[3]);
        *(float4*)(Dout + h * 32 + m0 + 4) = make_float4(od[4], od[5], od[6], od[7]);
    }
}

__global__ void __launch_bounds__(THREADS, 1)
npt_kernel(const float* __restrict__ x,
           const float* __restrict__ W1, const float* __restrict__ b1,
           const float* __restrict__ W2, const float* __restrict__ b2,
           const float* __restrict__ W3, const float* __restrict__ b3,
           const float* __restrict__ W4, const float* __restrict__ b4,
           float* __restrict__ out_res)
{
    extern __shared__ float sm[];
    const int tid  = threadIdx.x;
    const int d    = blockIdx.x >> 1;   // latent index
    const int half = blockIdx.x & 1;    // sample half [0..2048) / [2048..4096)

    // -------- load + transpose weights for this latent into SMEM --------
    {
        const int h = tid;  // 128 threads <-> 128 hidden units
        const float* w1r = W1 + (size_t)(d * 128 + h) * 65;
#pragma unroll
        for (int k = 0; k < 65; k++) sm[OFF_W1 + k * 128 + h] = w1r[k];

        const float* w2r = W2 + (size_t)(d * 128 + h) * 128;
        const float* w3r = W3 + (size_t)(d * 128 + h) * 128;
#pragma unroll
        for (int k4 = 0; k4 < 128; k4 += 4) {
            float4 v2 = *(const float4*)(w2r + k4);
            sm[OFF_W2 + (k4 + 0) * 128 + h] = v2.x;
            sm[OFF_W2 + (k4 + 1) * 128 + h] = v2.y;
            sm[OFF_W2 + (k4 + 2) * 128 + h] = v2.z;
            sm[OFF_W2 + (k4 + 3) * 128 + h] = v2.w;
            float4 v3 = *(const float4*)(w3r + k4);
            sm[OFF_W3 + (k4 + 0) * 128 + h] = v3.x;
            sm[OFF_W3 + (k4 + 1) * 128 + h] = v3.y;
            sm[OFF_W3 + (k4 + 2) * 128 + h] = v3.z;
            sm[OFF_W3 + (k4 + 3) * 128 + h] = v3.w;
        }
        sm[OFF_B1 + h] = b1[d * 128 + h];
        sm[OFF_B2 + h] = b2[d * 128 + h];
        sm[OFF_B3 + h] = b3[d * 128 + h];
        sm[OFF_W4 + h] = W4[d * 128 + h];
    }
    const float b4d = b4[d];
    __syncthreads();

    // micro-tile mapping: 4 m-groups x 32 h-groups
    const int m0 = (tid & 3) * 8;   // 8 samples per thread
    const int h0 = (tid >> 2) * 4;  // 4 hidden units per thread

    for (int tile = 0; tile < 64; tile++) {
        const int n0 = half * 2048 + tile * 32;
        const int b  = n0 >> 8;     // batch
        const int t0 = n0 & 255;    // time within batch

        // -------- stage input tile xl[k][m] (k<64: x[b,t,k]; k==64: x[b,t+1,d]) --------
        {
            float* xl = sm + OFF_BA1;  // BA1 is dead here; aliased as x-tile
            const int m = tid >> 2, part = tid & 3;
            const float* xr = x + ((size_t)(b * 257 + t0 + m)) * 64 + part * 16;
#pragma unroll
            for (int i = 0; i < 16; i += 4) {
                float4 v = *(const float4*)(xr + i);
                const int k = part * 16 + i;
                xl[(k + 0) * 32 + m] = v.x;
                xl[(k + 1) * 32 + m] = v.y;
                xl[(k + 2) * 32 + m] = v.z;
                xl[(k + 3) * 32 + m] = v.w;
            }
            if (tid < 32)
                xl[64 * 32 + tid] = x[((size_t)(b * 257 + t0 + tid + 1)) * 64 + d];
        }
        __syncthreads();

        // -------- Layer 1 (K=65, forward only) -> BA0 (a1), BD0 (d1 = s1 * W1[:,64]) --------
        {
            u64 accA[4][4];   // [h][m-pair]
#pragma unroll
            for (int i = 0; i < 4; i++)
#pragma unroll
                for (int j = 0; j < 4; j++) accA[i][j] = 0ull;

            const float* xl = sm + OFF_BA1;
            const float* Wt = sm + OFF_W1;
#pragma unroll 5
            for (int k = 0; k < 65; k++) {
                ulonglong2 aA = *(const ulonglong2*)(xl + k * 32 + m0);
                ulonglong2 aB = *(const ulonglong2*)(xl + k * 32 + m0 + 4);
                float4 wf = *(const float4*)(Wt + k * 128 + h0);
                u64 w[4] = { dup2(wf.x), dup2(wf.y), dup2(wf.z), dup2(wf.w) };
                u64 a[4] = { aA.x, aA.y, aB.x, aB.y };
#pragma unroll
                for (int h = 0; h < 4; h++)
#pragma unroll
                    for (int mp = 0; mp < 4; mp++)
                        accA[h][mp] = fma2(a[mp], w[h], accA[h][mp]);
            }
            float* Aout = sm + OFF_BA0;
            float* Dout = sm + OFF_BD0;
#pragma unroll
            for (int hp = 0; hp < 4; hp++) {
                const int h = h0 + hp;
                const float bias = sm[OFF_B1 + h];
                const float wc   = sm[OFF_W1 + 64 * 128 + h];
                float oa[8], od[8];
#pragma unroll
                for (int mp = 0; mp < 4; mp++) {
                    float2 pa = unpack2(accA[hp][mp]);
                    float p0 = pa.x + bias; float s0 = (p0 > 0.f) ? 1.f : SLOPE;
                    oa[2 * mp]     = p0 * s0;  od[2 * mp]     = s0 * wc;
                    float p1 = pa.y + bias; float s1 = (p1 > 0.f) ? 1.f : SLOPE;
                    oa[2 * mp + 1] = p1 * s1;  od[2 * mp + 1] = s1 * wc;
                }
                *(float4*)(Aout + h * 32 + m0)     = make_float4(oa[0], oa[1], oa[2], oa[3]);
                *(float4*)(Aout + h * 32 + m0 + 4) = make_float4(oa[4], oa[5], oa[6], oa[7]);
                *(float4*)(Dout + h * 32 + m0)     = make_float4(od[0], od[1], od[2], od[3]);
                *(float4*)(Dout + h * 32 + m0 + 4) = make_float4(od[4], od[5], od[6], od[7]);
            }
        }
        __syncthreads();

        // -------- Layer 2 fused fwd+deriv: BA0/BD0 -> BA1/BD1 --------
        gemm_fused(sm, OFF_BA0, OFF_BD0, OFF_W2, OFF_B2, OFF_BA1, OFF_BD1, m0, h0);
        __syncthreads();

        // -------- Layer 3 fused fwd+deriv: BA1/BD1 -> BA0/BD0 --------
        gemm_fused(sm, OFF_BA1, OFF_BD1, OFF_W3, OFF_B3, OFF_BA0, OFF_BD0, m0, h0);
        __syncthreads();

        // -------- Layer 4 reductions: residual + log|deriv| --------
        {
            float* red = sm + OFF_BA1;  // scratch aliases BA1 (dead)
            const int m = tid & 31, q = tid >> 5;   // 4 groups x 32 h each
            const float* A3 = sm + OFF_BA0;
            const float* D3 = sm + OFF_BD0;
            float pa = 0.f, pd = 0.f;
#pragma unroll
            for (int hh = 0; hh < 32; hh++) {
                const int h = q * 32 + hh;
                const float w = sm[OFF_W4 + h];
                pa += A3[h * 32 + m] * w;
                pd += D3[h * 32 + m] * w;
            }
            red[q * 32 + m]       = pa;
            red[128 + q * 32 + m] = pd;
            __syncthreads();
            if (tid < 32) {
                const int n = n0 + tid;
                float res = red[tid] + red[32 + tid] + red[64 + tid] + red[96 + tid] + b4d;
                out_res[(size_t)n * 64 + d] = res;
                float dv = red[128 + tid] + red[160 + tid] + red[192 + tid] + red[224 + tid];
                g_scratch[d * 4096 + n] = logf(fabsf(dv) + 1e-8f);
            }
        }
        __syncthreads();
    }
}

// deterministic sum over latents: out_logdet[n] = sum_d scratch[d][n]
__global__ void reduce_logdet_kernel(float* __restrict__ out_ld)
{
    const int n = blockIdx.x * blockDim.x + threadIdx.x;
    if (n < 4096) {
        float s = 0.f;
#pragma unroll
        for (int d = 0; d < 64; d++) s += g_scratch[d * 4096 + n];
        out_ld[n] = s;
    }
}

extern "C" void kernel_launch(void* const* d_in, const int* in_sizes, int n_in,
                              void* d_out, int out_size)
{
    const float* x  = (const float*)d_in[0];
    const float* W1 = (const float*)d_in[1];
    const float* b1 = (const float*)d_in[2];
    const float* W2 = (const float*)d_in[3];
    const float* b2 = (const float*)d_in[4];
    const float* W3 = (const float*)d_in[5];
    const float* b3 = (const float*)d_in[6];
    const float* W4 = (const float*)d_in[7];
    const float* b4 = (const float*)d_in[8];
    (void)in_sizes; (void)n_in; (void)out_size;

    float* out_res = (float*)d_out;                  // [16,256,64]
    float* out_ld  = (float*)d_out + 16 * 256 * 64;  // [16,256]

    const size_t smem = (size_t)SMEM_FLOATS * sizeof(float);  // 231,936 B
    cudaFuncSetAttribute(npt_kernel, cudaFuncAttributeMaxDynamicSharedMemorySize, (int)smem);

    npt_kernel<<<128, THREADS, smem>>>(x, W1, b1, W2, b2, W3, b3, W4, b4, out_res);
    reduce_logdet_kernel<<<16, 256>>>(out_ld);
}

// round 12
// speedup vs baseline: 3.6763x; 2.5115x over previous
#include <cuda_runtime.h>
#include <cstdint>

#define SLOPE 0.2f
#define THREADS 128

// ---------------- SMEM byte offsets ----------------
#define SM_RED    0        // 4 warps x 2 chains x 32 m floats = 1024 B
#define SM_CONST  1024     // b1,b2,b3,w4,w1c (5x128 f32) + xt (32 f32) = 2688 B
#define SM_XHI    3712     // [32 m][64 k] bf16, pitch 144 B
#define SM_XLO    8320
#define SM_W1HI   12928    // [128 h][64 k] bf16, pitch 144 B
#define SM_W1LO   31360
#define SM_AHI    49792    // [32 m][128 k] bf16, pitch 272 B (activations)
#define SM_ALO    58496
#define SM_DHI    67200    // derivative chain
#define SM_DLO    75904
#define SM_W2HI   84608    // [128 h][128 k] bf16, pitch 272 B
#define SM_W2LO   119424
#define SM_W3HI   154240
#define SM_W3LO   189056
#define SMEM_BYTES 223872

#define PITCH_W 272
#define PITCH_X 144

// deterministic cross-d logdet partials: scratch[d][n]
__device__ float g_scratch[64 * 4096];

// ================= helpers =================
__device__ __forceinline__ uint32_t smem_to_u32(const void* p) {
    uint32_t a;
    asm("{ .reg .u64 t; cvta.to.shared.u64 t, %1; cvt.u32.u64 %0, t; }" : "=r"(a) : "l"(p));
    return a;
}
// pack two f32 -> bf16x2, LOW halfword = first arg
__device__ __forceinline__ uint32_t packbf(float lo, float hi) {
    uint32_t r;
    asm("cvt.rn.bf16x2.f32 %0, %1, %2;" : "=r"(r) : "f"(hi), "f"(lo));
    return r;
}
__device__ __forceinline__ float lo_f(uint32_t p) { return __uint_as_float(p << 16); }
__device__ __forceinline__ float hi_f(uint32_t p) { return __uint_as_float(p & 0xFFFF0000u); }

__device__ __forceinline__ void ldsm4(uint32_t a, uint32_t* r) {
    asm volatile("ldmatrix.sync.aligned.m8n8.x4.shared.b16 {%0,%1,%2,%3}, [%4];"
        : "=r"(r[0]), "=r"(r[1]), "=r"(r[2]), "=r"(r[3]) : "r"(a));
}
__device__ __forceinline__ void stsm4t(uint32_t a, uint32_t r0, uint32_t r1, uint32_t r2, uint32_t r3) {
    asm volatile("stmatrix.sync.aligned.m8n8.x4.trans.shared.b16 [%0], {%1,%2,%3,%4};"
        :: "r"(a), "r"(r0), "r"(r1), "r"(r2), "r"(r3) : "memory");
}
__device__ __forceinline__ void mma_bf16(float* d, const uint32_t* a, uint32_t b0, uint32_t b1) {
    asm volatile("mma.sync.aligned.m16n8k16.row.col.f32.bf16.bf16.f32 "
        "{%0,%1,%2,%3}, {%4,%5,%6,%7}, {%8,%9}, {%0,%1,%2,%3};"
        : "+f"(d[0]), "+f"(d[1]), "+f"(d[2]), "+f"(d[3])
        : "r"(a[0]), "r"(a[1]), "r"(a[2]), "r"(a[3]), "r"(b0), "r"(b1));
}

// split 8 fp32 into bf16 hi/lo packed words and store 16B each
__device__ __forceinline__ void split_store8(const float* v, char* dstHi, char* dstLo) {
    uint32_t h0 = packbf(v[0], v[1]), h1 = packbf(v[2], v[3]);
    uint32_t h2 = packbf(v[4], v[5]), h3 = packbf(v[6], v[7]);
    uint32_t l0 = packbf(v[0] - lo_f(h0), v[1] - hi_f(h0));
    uint32_t l1 = packbf(v[2] - lo_f(h1), v[3] - hi_f(h1));
    uint32_t l2 = packbf(v[4] - lo_f(h2), v[5] - hi_f(h2));
    uint32_t l3 = packbf(v[6] - lo_f(h3), v[7] - hi_f(h3));
    *(uint4*)dstHi = make_uint4(h0, h1, h2, h3);
    *(uint4*)dstLo = make_uint4(l0, l1, l2, l3);
}

// aligned source (stride multiple of 4 floats): float4 loads
__device__ __forceinline__ void stage_row_aligned(const float* src, char* dstHi, char* dstLo, int K) {
    for (int k = 0; k < K; k += 8) {
        float v[8];
        float4 va = *(const float4*)(src + k);
        float4 vb = *(const float4*)(src + k + 4);
        v[0] = va.x; v[1] = va.y; v[2] = va.z; v[3] = va.w;
        v[4] = vb.x; v[5] = vb.y; v[6] = vb.z; v[7] = vb.w;
        split_store8(v, dstHi + k * 2, dstLo + k * 2);
    }
}

// UNALIGNED source (W1 rows: 65-float stride) -> scalar loads only
__device__ __forceinline__ void stage_row_unaligned(const float* src, char* dstHi, char* dstLo, int K) {
    for (int k = 0; k < K; k += 8) {
        float v[8];
#pragma unroll
        for (int i = 0; i < 8; i++) v[i] = src[k + i];
        split_store8(v, dstHi + k * 2, dstLo + k * 2);
    }
}

// epilogue store: 32h x 32m block of a/d values -> bf16 hi/lo tiles via stmatrix.trans
__device__ __forceinline__ void store_ad(
    uint32_t rAH, uint32_t rAL, uint32_t rDH, uint32_t rDL, uint32_t hc2,
    const float (&aV)[4][4], const float (&dV)[4][4], int rh)
{
    uint32_t ah[4], al[4], dh[4], dl[4];
#pragma unroll
    for (int nt = 0; nt < 4; nt++) {
        float a0 = aV[nt][rh * 2], a1 = aV[nt][rh * 2 + 1];
        uint32_t hp = packbf(a0, a1);
        ah[nt] = hp;
        al[nt] = packbf(a0 - lo_f(hp), a1 - hi_f(hp));
        float d0 = dV[nt][rh * 2], d1 = dV[nt][rh * 2 + 1];
        uint32_t hq = packbf(d0, d1);
        dh[nt] = hq;
        dl[nt] = packbf(d0 - lo_f(hq), d1 - hi_f(hq));
    }
    stsm4t(rAH + hc2, ah[0], ah[1], ah[2], ah[3]);
    stsm4t(rAL + hc2, al[0], al[1], al[2], al[3]);
    stsm4t(rDH + hc2, dh[0], dh[1], dh[2], dh[3]);
    stsm4t(rDL + hc2, dl[0], dl[1], dl[2], dl[3]);
}

// fused fwd+deriv layer: 8 k-steps, 3-term bf16 split, per-warp 2mt x 4nt accums
__device__ __forceinline__ void layer_fused(
    uint32_t wHiA, uint32_t wLoA,
    uint32_t aHiB, uint32_t aLoB, uint32_t dHiB, uint32_t dLoB,
    float (&F)[2][4][4], float (&G)[2][4][4])
{
#pragma unroll
    for (int ks = 0; ks < 8; ks++) {
        const uint32_t kb = ks * 32;
        uint32_t wh0[4], wh1[4], wl0[4], wl1[4];
        ldsm4(wHiA + kb, wh0); ldsm4(wHiA + kb + 16 * PITCH_W, wh1);
        ldsm4(wLoA + kb, wl0); ldsm4(wLoA + kb + 16 * PITCH_W, wl1);
        uint32_t bah[8], bal[8], bdh[8], bdl[8];
        ldsm4(aHiB + kb, bah); ldsm4(aHiB + kb + 16 * PITCH_W, bah + 4);
        ldsm4(aLoB + kb, bal); ldsm4(aLoB + kb + 16 * PITCH_W, bal + 4);
        ldsm4(dHiB + kb, bdh); ldsm4(dHiB + kb + 16 * PITCH_W, bdh + 4);
        ldsm4(dLoB + kb, bdl); ldsm4(dLoB + kb + 16 * PITCH_W, bdl + 4);
#pragma unroll
        for (int mt = 0; mt < 2; mt++) {
            const uint32_t* wh = mt ? wh1 : wh0;
            const uint32_t* wl = mt ? wl1 : wl0;
#pragma unroll
            for (int nt = 0; nt < 4; nt++) {
                mma_bf16(F[mt][nt], wh, bah[2 * nt], bah[2 * nt + 1]);
                mma_bf16(F[mt][nt], wh, bal[2 * nt], bal[2 * nt + 1]);
                mma_bf16(F[mt][nt], wl, bah[2 * nt], bah[2 * nt + 1]);
                mma_bf16(G[mt][nt], wh, bdh[2 * nt], bdh[2 * nt + 1]);
                mma_bf16(G[mt][nt], wh, bdl[2 * nt], bdl[2 * nt + 1]);
                mma_bf16(G[mt][nt], wl, bdh[2 * nt], bdh[2 * nt + 1]);
            }
        }
    }
}

__global__ void __launch_bounds__(THREADS, 1)
npt_kernel(const float* __restrict__ x,
           const float* __restrict__ W1, const float* __restrict__ b1,
           const float* __restrict__ W2, const float* __restrict__ b2,
           const float* __restrict__ W3, const float* __restrict__ b3,
           const float* __restrict__ W4, const float* __restrict__ b4,
           float* __restrict__ out_res)
{
    extern __shared__ char smem[];
    const uint32_t sb = smem_to_u32(smem);
    float* cst = (float*)(smem + SM_CONST);
    float* red = (float*)(smem + SM_RED);
    const int tid  = threadIdx.x;
    const int warp = tid >> 5;
    const int lane = tid & 31;
    const int d    = blockIdx.x >> 1;
    const int half = blockIdx.x & 1;

    // -------- stage weights (thread h = tid) + consts --------
    {
        const int h = tid;
        const float* w1r = W1 + (size_t)(d * 128 + h) * 65;   // 65-float stride: UNALIGNED rows
        stage_row_unaligned(w1r, smem + SM_W1HI + h * PITCH_X, smem + SM_W1LO + h * PITCH_X, 64);
        stage_row_aligned(W2 + (size_t)(d * 128 + h) * 128,
                          smem + SM_W2HI + h * PITCH_W, smem + SM_W2LO + h * PITCH_W, 128);
        stage_row_aligned(W3 + (size_t)(d * 128 + h) * 128,
                          smem + SM_W3HI + h * PITCH_W, smem + SM_W3LO + h * PITCH_W, 128);
        cst[h]       = b1[d * 128 + h];
        cst[128 + h] = b2[d * 128 + h];
        cst[256 + h] = b3[d * 128 + h];
        cst[384 + h] = W4[d * 128 + h];
        cst[512 + h] = w1r[64];
    }
    const float b4d = b4[d];
    __syncthreads();

    // per-thread h-dependent constants (h = warp*32 + mt*16 + rh*8 + lane/4)
    float b1v[2][2], b2v[2][2], b3v[2][2], w4v[2][2], w1cv[2][2];
#pragma unroll
    for (int mt = 0; mt < 2; mt++)
#pragma unroll
        for (int rh = 0; rh < 2; rh++) {
            const int hh = warp * 32 + mt * 16 + rh * 8 + (lane >> 2);
            b1v[mt][rh]  = cst[hh];
            b2v[mt][rh]  = cst[128 + hh];
            b3v[mt][rh]  = cst[256 + hh];
            w4v[mt][rh]  = cst[384 + hh];
            w1cv[mt][rh] = cst[512 + hh];
        }

    // ldmatrix lane offsets
    const uint32_t aOffW = (uint32_t)(lane & 15) * PITCH_W + (uint32_t)(lane >> 4) * 16;
    const uint32_t bOffW = (uint32_t)((lane & 7) + ((lane >> 4) << 3)) * PITCH_W
                         + (uint32_t)((lane >> 3) & 1) * 16;
    const uint32_t aOffX = (uint32_t)(lane & 15) * PITCH_X + (uint32_t)(lane >> 4) * 16;
    const uint32_t bOffX = (uint32_t)((lane & 7) + ((lane >> 4) << 3)) * PITCH_X
                         + (uint32_t)((lane >> 3) & 1) * 16;

    const uint32_t w1hiA = sb + SM_W1HI + warp * 32 * PITCH_X + aOffX;
    const uint32_t w1loA = sb + SM_W1LO + warp * 32 * PITCH_X + aOffX;
    const uint32_t w2hiA = sb + SM_W2HI + warp * 32 * PITCH_W + aOffW;
    const uint32_t w2loA = sb + SM_W2LO + warp * 32 * PITCH_W + aOffW;
    const uint32_t w3hiA = sb + SM_W3HI + warp * 32 * PITCH_W + aOffW;
    const uint32_t w3loA = sb + SM_W3LO + warp * 32 * PITCH_W + aOffW;
    const uint32_t xhiB  = sb + SM_XHI + bOffX;
    const uint32_t xloB  = sb + SM_XLO + bOffX;
    const uint32_t ahiB  = sb + SM_AHI + bOffW;
    const uint32_t aloB  = sb + SM_ALO + bOffW;
    const uint32_t dhiB  = sb + SM_DHI + bOffW;
    const uint32_t dloB  = sb + SM_DLO + bOffW;
    // stmatrix destination row bases (row = m = lane)
    const uint32_t rowAH = sb + SM_AHI + lane * PITCH_W;
    const uint32_t rowAL = sb + SM_ALO + lane * PITCH_W;
    const uint32_t rowDH = sb + SM_DHI + lane * PITCH_W;
    const uint32_t rowDL = sb + SM_DLO + lane * PITCH_W;

    for (int tile = 0; tile < 64; tile++) {
        const int n0 = half * 2048 + tile * 32;
        const int b  = n0 >> 8;
        const int t0 = n0 & 255;

        // -------- stage x tile: [32 m][64 k] hi/lo + xt[32] --------
        {
            const int m = tid >> 2, kq = tid & 3;
            const float* xr = x + ((size_t)(b * 257 + t0 + m)) * 64 + kq * 16;
            float v[16];
#pragma unroll
            for (int i = 0; i < 16; i += 4) {
                float4 t = *(const float4*)(xr + i);
                v[i] = t.x; v[i + 1] = t.y; v[i + 2] = t.z; v[i + 3] = t.w;
            }
            char* rH = smem + SM_XHI + m * PITCH_X + kq * 32;
            char* rL = smem + SM_XLO + m * PITCH_X + kq * 32;
            split_store8(v,     rH,      rL);
            split_store8(v + 8, rH + 16, rL + 16);
            if (tid < 32)
                cst[640 + tid] = x[((size_t)(b * 257 + t0 + tid + 1)) * 64 + d];
        }
        __syncthreads();   // S1: X + xt ready

        float F[2][4][4], G[2][4][4];
#pragma unroll
        for (int i = 0; i < 2; i++)
#pragma unroll
            for (int j = 0; j < 4; j++)
#pragma unroll
                for (int r = 0; r < 4; r++) F[i][j][r] = 0.f;

        // ======== Layer 1 mma (fwd only, K=64) ========
#pragma unroll
        for (int ks = 0; ks < 4; ks++) {
            const uint32_t kb = ks * 32;
            uint32_t wh0[4], wh1[4], wl0[4], wl1[4];
            ldsm4(w1hiA + kb, wh0); ldsm4(w1hiA + kb + 16 * PITCH_X, wh1);
            ldsm4(w1loA + kb, wl0); ldsm4(w1loA + kb + 16 * PITCH_X, wl1);
            uint32_t bh[8], bl[8];
            ldsm4(xhiB + kb, bh); ldsm4(xhiB + kb + 16 * PITCH_X, bh + 4);
            ldsm4(xloB + kb, bl); ldsm4(xloB + kb + 16 * PITCH_X, bl + 4);
#pragma unroll
            for (int mt = 0; mt < 2; mt++) {
                const uint32_t* wh = mt ? wh1 : wh0;
                const uint32_t* wl = mt ? wl1 : wl0;
#pragma unroll
                for (int nt = 0; nt < 4; nt++) {
                    mma_bf16(F[mt][nt], wh, bh[2 * nt], bh[2 * nt + 1]);
                    mma_bf16(F[mt][nt], wh, bl[2 * nt], bl[2 * nt + 1]);
                    mma_bf16(F[mt][nt], wl, bh[2 * nt], bh[2 * nt + 1]);
                }
            }
        }

        // ---- L1 epilogue: rank-1 x_t term + bias + leaky; d1 = s1*w1c ----
        {
            float xtv[4][2];
            const int mb = 2 * (lane & 3);
#pragma unroll
            for (int nt = 0; nt < 4; nt++) {
                xtv[nt][0] = cst[640 + nt * 8 + mb];
                xtv[nt][1] = cst[640 + nt * 8 + mb + 1];
            }
#pragma unroll
            for (int mt = 0; mt < 2; mt++) {
                float aV[4][4], dV[4][4];
#pragma unroll
                for (int nt = 0; nt < 4; nt++)
#pragma unroll
                    for (int r = 0; r < 4; r++) {
                        const int rh = r >> 1;
                        float p = F[mt][nt][r] + b1v[mt][rh] + w1cv[mt][rh] * xtv[nt][r & 1];
                        float s = (p > 0.f) ? 1.f : SLOPE;
                        aV[nt][r] = p * s;
                        dV[nt][r] = s * w1cv[mt][rh];
                    }
#pragma unroll
                for (int rh = 0; rh < 2; rh++)
                    store_ad(rowAH, rowAL, rowDH, rowDL,
                             (uint32_t)((warp * 32 + mt * 16 + rh * 8) * 2), aV, dV, rh);
            }
        }
        __syncthreads();   // S2: A/D tiles ready

        // ======== Layer 2 ========
#pragma unroll
        for (int i = 0; i < 2; i++)
#pragma unroll
            for (int j = 0; j < 4; j++)
#pragma unroll
                for (int r = 0; r < 4; r++) { F[i][j][r] = 0.f; G[i][j][r] = 0.f; }
        layer_fused(w2hiA, w2loA, ahiB, aloB, dhiB, dloB, F, G);
        __syncthreads();   // S3: all warps done reading A/D

#pragma unroll
        for (int mt = 0; mt < 2; mt++) {
            float aV[4][4], dV[4][4];
#pragma unroll
            for (int nt = 0; nt < 4; nt++)
#pragma unroll
                for (int r = 0; r < 4; r++) {
                    const int rh = r >> 1;
                    float p = F[mt][nt][r] + b2v[mt][rh];
                    float s = (p > 0.f) ? 1.f : SLOPE;
                    aV[nt][r] = p * s;
                    dV[nt][r] = s * G[mt][nt][r];
                }
#pragma unroll
            for (int rh = 0; rh < 2; rh++)
                store_ad(rowAH, rowAL, rowDH, rowDL,
                         (uint32_t)((warp * 32 + mt * 16 + rh * 8) * 2), aV, dV, rh);
        }
        __syncthreads();   // S4: A/D tiles ready for L3

        // ======== Layer 3 ========
#pragma unroll
        for (int i = 0; i < 2; i++)
#pragma unroll
            for (int j = 0; j < 4; j++)
#pragma unroll
                for (int r = 0; r < 4; r++) { F[i][j][r] = 0.f; G[i][j][r] = 0.f; }
        layer_fused(w3hiA, w3loA, ahiB, aloB, dhiB, dloB, F, G);

        // ---- L3 epilogue -> w4-weighted partials, shuffle reduce over h ----
        {
            float pA[4][2], pD[4][2];
#pragma unroll
            for (int nt = 0; nt < 4; nt++) { pA[nt][0] = pA[nt][1] = 0.f; pD[nt][0] = pD[nt][1] = 0.f; }
#pragma unroll
            for (int mt = 0; mt < 2; mt++)
#pragma unroll
                for (int nt = 0; nt < 4; nt++)
#pragma unroll
                    for (int r = 0; r < 4; r++) {
                        const int rh = r >> 1;
                        float p = F[mt][nt][r] + b3v[mt][rh];
                        float s = (p > 0.f) ? 1.f : SLOPE;
                        pA[nt][r & 1] += w4v[mt][rh] * (p * s);
                        pD[nt][r & 1] += w4v[mt][rh] * (s * G[mt][nt][r]);
                    }
#pragma unroll
            for (int nt = 0; nt < 4; nt++)
#pragma unroll
                for (int c = 0; c < 2; c++) {
                    float v = pA[nt][c];
                    v += __shfl_xor_sync(0xffffffffu, v, 4);
                    v += __shfl_xor_sync(0xffffffffu, v, 8);
                    v += __shfl_xor_sync(0xffffffffu, v, 16);
                    pA[nt][c] = v;
                    float u = pD[nt][c];
                    u += __shfl_xor_sync(0xffffffffu, u, 4);
                    u += __shfl_xor_sync(0xffffffffu, u, 8);
                    u += __shfl_xor_sync(0xffffffffu, u, 16);
                    pD[nt][c] = u;
                }
            if (lane < 4) {
#pragma unroll
                for (int nt = 0; nt < 4; nt++) {
                    red[warp * 64 + nt * 8 + 2 * lane]          = pA[nt][0];
                    red[warp * 64 + nt * 8 + 2 * lane + 1]      = pA[nt][1];
                    red[warp * 64 + 32 + nt * 8 + 2 * lane]     = pD[nt][0];
                    red[warp * 64 + 32 + nt * 8 + 2 * lane + 1] = pD[nt][1];
                }
            }
        }
        __syncthreads();   // S5: red ready

        if (tid < 32) {
            const int n = n0 + tid;
            float res = red[tid] + red[64 + tid] + red[128 + tid] + red[192 + tid] + b4d;
            float dv  = red[32 + tid] + red[96 + tid] + red[160 + tid] + red[224 + tid];
            out_res[(size_t)n * 64 + d] = res;
            g_scratch[d * 4096 + n] = logf(fabsf(dv) + 1e-8f);
        }
        __syncthreads();   // S6: red consumed, safe to reuse next tile
    }
}

// deterministic sum over latents: out_logdet[n] = sum_d scratch[d][n]
__global__ void reduce_logdet_kernel(float* __restrict__ out_ld)
{
    const int n = blockIdx.x * blockDim.x + threadIdx.x;
    if (n < 4096) {
        float s = 0.f;
#pragma unroll
        for (int d = 0; d < 64; d++) s += g_scratch[d * 4096 + n];
        out_ld[n] = s;
    }
}

extern "C" void kernel_launch(void* const* d_in, const int* in_sizes, int n_in,
                              void* d_out, int out_size)
{
    const float* x  = (const float*)d_in[0];
    const float* W1 = (const float*)d_in[1];
    const float* b1 = (const float*)d_in[2];
    const float* W2 = (const float*)d_in[3];
    const float* b2 = (const float*)d_in[4];
    const float* W3 = (const float*)d_in[5];
    const float* b3 = (const float*)d_in[6];
    const float* W4 = (const float*)d_in[7];
    const float* b4 = (const float*)d_in[8];
    (void)in_sizes; (void)n_in; (void)out_size;

    float* out_res = (float*)d_out;                  // [16,256,64]
    float* out_ld  = (float*)d_out + 16 * 256 * 64;  // [16,256]

    cudaFuncSetAttribute(npt_kernel, cudaFuncAttributeMaxDynamicSharedMemorySize, SMEM_BYTES);

    npt_kernel<<<128, THREADS, SMEM_BYTES>>>(x, W1, b1, W2, b2, W3, b3, W4, b4, out_res);
    reduce_logdet_kernel<<<16, 256>>>(out_ld);
}

// round 13
// speedup vs baseline: 3.9699x; 1.0798x over previous
#include <cuda_runtime.h>
#include <cstdint>

#define SLOPE 0.2f
#define THREADS 256

// ---------------- SMEM byte offsets ----------------
#define SM_RED    0        // 8 warps x 2 chains x 32 m floats = 2048 B
#define SM_CONST  2048     // b1,b2,b3,w4,w1c (5x128 f32) + xt (32 f32) = 2688 B
#define SM_XHI    4736     // [32 m][64 k] bf16, pitch 144 B
#define SM_XLO    9344
#define SM_W1HI   13952    // [128 h][64 k] bf16, pitch 144 B
#define SM_W1LO   32384
#define SM_AHI    50816    // [32 m][128 k] bf16, pitch 272 B (activations)
#define SM_ALO    59520
#define SM_DHI    68224    // derivative chain
#define SM_DLO    76928
#define SM_W2HI   85632    // [128 h][128 k] bf16, pitch 272 B
#define SM_W2LO   120448
#define SM_W3HI   155264
#define SM_W3LO   190080
#define SMEM_BYTES 224896

#define PITCH_W 272
#define PITCH_X 144

// deterministic cross-d logdet partials: scratch[d][n]
__device__ float g_scratch[64 * 4096];

// ================= helpers =================
__device__ __forceinline__ uint32_t smem_to_u32(const void* p) {
    uint32_t a;
    asm("{ .reg .u64 t; cvta.to.shared.u64 t, %1; cvt.u32.u64 %0, t; }" : "=r"(a) : "l"(p));
    return a;
}
// pack two f32 -> bf16x2, LOW halfword = first arg
__device__ __forceinline__ uint32_t packbf(float lo, float hi) {
    uint32_t r;
    asm("cvt.rn.bf16x2.f32 %0, %1, %2;" : "=r"(r) : "f"(hi), "f"(lo));
    return r;
}
__device__ __forceinline__ float lo_f(uint32_t p) { return __uint_as_float(p << 16); }
__device__ __forceinline__ float hi_f(uint32_t p) { return __uint_as_float(p & 0xFFFF0000u); }

__device__ __forceinline__ void ldsm4(uint32_t a, uint32_t* r) {
    asm volatile("ldmatrix.sync.aligned.m8n8.x4.shared.b16 {%0,%1,%2,%3}, [%4];"
        : "=r"(r[0]), "=r"(r[1]), "=r"(r[2]), "=r"(r[3]) : "r"(a));
}
__device__ __forceinline__ void stsm4t(uint32_t a, uint32_t r0, uint32_t r1, uint32_t r2, uint32_t r3) {
    asm volatile("stmatrix.sync.aligned.m8n8.x4.trans.shared.b16 [%0], {%1,%2,%3,%4};"
        :: "r"(a), "r"(r0), "r"(r1), "r"(r2), "r"(r3) : "memory");
}
__device__ __forceinline__ void mma_bf16(float* d, const uint32_t* a, uint32_t b0, uint32_t b1) {
    asm volatile("mma.sync.aligned.m16n8k16.row.col.f32.bf16.bf16.f32 "
        "{%0,%1,%2,%3}, {%4,%5,%6,%7}, {%8,%9}, {%0,%1,%2,%3};"
        : "+f"(d[0]), "+f"(d[1]), "+f"(d[2]), "+f"(d[3])
        : "r"(a[0]), "r"(a[1]), "r"(a[2]), "r"(a[3]), "r"(b0), "r"(b1));
}

// split 8 fp32 into bf16 hi/lo packed words and store 16B each
__device__ __forceinline__ void split_store8(const float* v, char* dstHi, char* dstLo) {
    uint32_t h0 = packbf(v[0], v[1]), h1 = packbf(v[2], v[3]);
    uint32_t h2 = packbf(v[4], v[5]), h3 = packbf(v[6], v[7]);
    uint32_t l0 = packbf(v[0] - lo_f(h0), v[1] - hi_f(h0));
    uint32_t l1 = packbf(v[2] - lo_f(h1), v[3] - hi_f(h1));
    uint32_t l2 = packbf(v[4] - lo_f(h2), v[5] - hi_f(h2));
    uint32_t l3 = packbf(v[6] - lo_f(h3), v[7] - hi_f(h3));
    *(uint4*)dstHi = make_uint4(h0, h1, h2, h3);
    *(uint4*)dstLo = make_uint4(l0, l1, l2, l3);
}

// aligned source (stride multiple of 4 floats): float4 loads
__device__ __forceinline__ void stage_row_aligned(const float* src, char* dstHi, char* dstLo, int K) {
    for (int k = 0; k < K; k += 8) {
        float v[8];
        float4 va = *(const float4*)(src + k);
        float4 vb = *(const float4*)(src + k + 4);
        v[0] = va.x; v[1] = va.y; v[2] = va.z; v[3] = va.w;
        v[4] = vb.x; v[5] = vb.y; v[6] = vb.z; v[7] = vb.w;
        split_store8(v, dstHi + k * 2, dstLo + k * 2);
    }
}

// UNALIGNED source (W1 rows: 65-float stride) -> scalar loads only
__device__ __forceinline__ void stage_row_unaligned(const float* src, char* dstHi, char* dstLo, int K) {
    for (int k = 0; k < K; k += 8) {
        float v[8];
#pragma unroll
        for (int i = 0; i < 8; i++) v[i] = src[k + i];
        split_store8(v, dstHi + k * 2, dstLo + k * 2);
    }
}

// epilogue store: 16h x 32m block of a/d values -> bf16 hi/lo tiles via stmatrix.trans
__device__ __forceinline__ void store_ad(
    uint32_t rAH, uint32_t rAL, uint32_t rDH, uint32_t rDL, uint32_t hc2,
    const float (&aV)[4][4], const float (&dV)[4][4], int rh)
{
    uint32_t ah[4], al[4], dh[4], dl[4];
#pragma unroll
    for (int nt = 0; nt < 4; nt++) {
        float a0 = aV[nt][rh * 2], a1 = aV[nt][rh * 2 + 1];
        uint32_t hp = packbf(a0, a1);
        ah[nt] = hp;
        al[nt] = packbf(a0 - lo_f(hp), a1 - hi_f(hp));
        float d0 = dV[nt][rh * 2], d1 = dV[nt][rh * 2 + 1];
        uint32_t hq = packbf(d0, d1);
        dh[nt] = hq;
        dl[nt] = packbf(d0 - lo_f(hq), d1 - hi_f(hq));
    }
    stsm4t(rAH + hc2, ah[0], ah[1], ah[2], ah[3]);
    stsm4t(rAL + hc2, al[0], al[1], al[2], al[3]);
    stsm4t(rDH + hc2, dh[0], dh[1], dh[2], dh[3]);
    stsm4t(rDL + hc2, dl[0], dl[1], dl[2], dl[3]);
}

// fused fwd+deriv layer: 8 k-steps, 3-term bf16 split, per-warp 16h x 32m (4nt accums)
__device__ __forceinline__ void layer_fused(
    uint32_t wHiA, uint32_t wLoA,
    uint32_t aHiB, uint32_t aLoB, uint32_t dHiB, uint32_t dLoB,
    float (&F)[4][4], float (&G)[4][4])
{
#pragma unroll
    for (int ks = 0; ks < 8; ks++) {
        const uint32_t kb = ks * 32;
        uint32_t wh[4], wl[4];
        ldsm4(wHiA + kb, wh);
        ldsm4(wLoA + kb, wl);
        uint32_t bah[8], bal[8], bdh[8], bdl[8];
        ldsm4(aHiB + kb, bah); ldsm4(aHiB + kb + 16 * PITCH_W, bah + 4);
        ldsm4(aLoB + kb, bal); ldsm4(aLoB + kb + 16 * PITCH_W, bal + 4);
        ldsm4(dHiB + kb, bdh); ldsm4(dHiB + kb + 16 * PITCH_W, bdh + 4);
        ldsm4(dLoB + kb, bdl); ldsm4(dLoB + kb + 16 * PITCH_W, bdl + 4);
#pragma unroll
        for (int nt = 0; nt < 4; nt++) {
            mma_bf16(F[nt], wh, bah[2 * nt], bah[2 * nt + 1]);
            mma_bf16(F[nt], wh, bal[2 * nt], bal[2 * nt + 1]);
            mma_bf16(F[nt], wl, bah[2 * nt], bah[2 * nt + 1]);
            mma_bf16(G[nt], wh, bdh[2 * nt], bdh[2 * nt + 1]);
            mma_bf16(G[nt], wh, bdl[2 * nt], bdl[2 * nt + 1]);
            mma_bf16(G[nt], wl, bdh[2 * nt], bdh[2 * nt + 1]);
        }
    }
}

__global__ void __launch_bounds__(THREADS, 1)
npt_kernel(const float* __restrict__ x,
           const float* __restrict__ W1, const float* __restrict__ b1,
           const float* __restrict__ W2, const float* __restrict__ b2,
           const float* __restrict__ W3, const float* __restrict__ b3,
           const float* __restrict__ W4, const float* __restrict__ b4,
           float* __restrict__ out_res)
{
    extern __shared__ char smem[];
    const uint32_t sb = smem_to_u32(smem);
    float* cst = (float*)(smem + SM_CONST);
    float* red = (float*)(smem + SM_RED);
    const int tid  = threadIdx.x;
    const int warp = tid >> 5;        // 0..7; warp owns h in [warp*16, warp*16+16)
    const int lane = tid & 31;
    const int d    = blockIdx.x >> 1;
    const int half = blockIdx.x & 1;

    // -------- stage weights + consts (split across 256 threads) --------
    if (tid < 128) {
        const int h = tid;
        const float* w1r = W1 + (size_t)(d * 128 + h) * 65;   // 65-float stride: UNALIGNED
        stage_row_unaligned(w1r, smem + SM_W1HI + h * PITCH_X, smem + SM_W1LO + h * PITCH_X, 64);
        cst[h]       = b1[d * 128 + h];
        cst[128 + h] = b2[d * 128 + h];
        cst[256 + h] = b3[d * 128 + h];
        cst[384 + h] = W4[d * 128 + h];
        cst[512 + h] = w1r[64];
    } else {
        const int h = tid - 128;
        stage_row_aligned(W2 + (size_t)(d * 128 + h) * 128,
                          smem + SM_W2HI + h * PITCH_W, smem + SM_W2LO + h * PITCH_W, 128);
        stage_row_aligned(W3 + (size_t)(d * 128 + h) * 128,
                          smem + SM_W3HI + h * PITCH_W, smem + SM_W3LO + h * PITCH_W, 128);
    }
    const float b4d = b4[d];
    __syncthreads();

    // per-thread h-dependent constants (h = warp*16 + rh*8 + lane/4)
    float b1v[2], b2v[2], b3v[2], w4v[2], w1cv[2];
#pragma unroll
    for (int rh = 0; rh < 2; rh++) {
        const int hh = warp * 16 + rh * 8 + (lane >> 2);
        b1v[rh]  = cst[hh];
        b2v[rh]  = cst[128 + hh];
        b3v[rh]  = cst[256 + hh];
        w4v[rh]  = cst[384 + hh];
        w1cv[rh] = cst[512 + hh];
    }

    // ldmatrix lane offsets
    const uint32_t aOffW = (uint32_t)(lane & 15) * PITCH_W + (uint32_t)(lane >> 4) * 16;
    const uint32_t bOffW = (uint32_t)((lane & 7) + ((lane >> 4) << 3)) * PITCH_W
                         + (uint32_t)((lane >> 3) & 1) * 16;
    const uint32_t aOffX = (uint32_t)(lane & 15) * PITCH_X + (uint32_t)(lane >> 4) * 16;
    const uint32_t bOffX = (uint32_t)((lane & 7) + ((lane >> 4) << 3)) * PITCH_X
                         + (uint32_t)((lane >> 3) & 1) * 16;

    const uint32_t w1hiA = sb + SM_W1HI + warp * 16 * PITCH_X + aOffX;
    const uint32_t w1loA = sb + SM_W1LO + warp * 16 * PITCH_X + aOffX;
    const uint32_t w2hiA = sb + SM_W2HI + warp * 16 * PITCH_W + aOffW;
    const uint32_t w2loA = sb + SM_W2LO + warp * 16 * PITCH_W + aOffW;
    const uint32_t w3hiA = sb + SM_W3HI + warp * 16 * PITCH_W + aOffW;
    const uint32_t w3loA = sb + SM_W3LO + warp * 16 * PITCH_W + aOffW;
    const uint32_t xhiB  = sb + SM_XHI + bOffX;
    const uint32_t xloB  = sb + SM_XLO + bOffX;
    const uint32_t ahiB  = sb + SM_AHI + bOffW;
    const uint32_t aloB  = sb + SM_ALO + bOffW;
    const uint32_t dhiB  = sb + SM_DHI + bOffW;
    const uint32_t dloB  = sb + SM_DLO + bOffW;
    // stmatrix destination row bases (row = m = lane)
    const uint32_t rowAH = sb + SM_AHI + lane * PITCH_W;
    const uint32_t rowAL = sb + SM_ALO + lane * PITCH_W;
    const uint32_t rowDH = sb + SM_DHI + lane * PITCH_W;
    const uint32_t rowDL = sb + SM_DLO + lane * PITCH_W;

    for (int tile = 0; tile < 64; tile++) {
        const int n0 = half * 2048 + tile * 32;
        const int b  = n0 >> 8;
        const int t0 = n0 & 255;

        // -------- stage x tile: [32 m][64 k] hi/lo + xt[32] (256 threads) --------
        {
            const int m = tid >> 3, kq = tid & 7;   // 32 rows x 8 threads x 8 floats
            const float* xr = x + ((size_t)(b * 257 + t0 + m)) * 64 + kq * 8;
            float v[8];
            float4 ta = *(const float4*)(xr);
            float4 tb = *(const float4*)(xr + 4);
            v[0] = ta.x; v[1] = ta.y; v[2] = ta.z; v[3] = ta.w;
            v[4] = tb.x; v[5] = tb.y; v[6] = tb.z; v[7] = tb.w;
            char* rH = smem + SM_XHI + m * PITCH_X + kq * 16;
            char* rL = smem + SM_XLO + m * PITCH_X + kq * 16;
            split_store8(v, rH, rL);
            if (tid < 32)
                cst[640 + tid] = x[((size_t)(b * 257 + t0 + tid + 1)) * 64 + d];
        }
        __syncthreads();   // S1: X + xt ready

        float F[4][4], G[4][4];
#pragma unroll
        for (int j = 0; j < 4; j++)
#pragma unroll
            for (int r = 0; r < 4; r++) F[j][r] = 0.f;

        // ======== Layer 1 mma (fwd only, K=64) ========
#pragma unroll
        for (int ks = 0; ks < 4; ks++) {
            const uint32_t kb = ks * 32;
            uint32_t wh[4], wl[4];
            ldsm4(w1hiA + kb, wh);
            ldsm4(w1loA + kb, wl);
            uint32_t bh[8], bl[8];
            ldsm4(xhiB + kb, bh); ldsm4(xhiB + kb + 16 * PITCH_X, bh + 4);
            ldsm4(xloB + kb, bl); ldsm4(xloB + kb + 16 * PITCH_X, bl + 4);
#pragma unroll
            for (int nt = 0; nt < 4; nt++) {
                mma_bf16(F[nt], wh, bh[2 * nt], bh[2 * nt + 1]);
                mma_bf16(F[nt], wh, bl[2 * nt], bl[2 * nt + 1]);
                mma_bf16(F[nt], wl, bh[2 * nt], bh[2 * nt + 1]);
            }
        }

        // ---- L1 epilogue: rank-1 x_t term + bias + leaky; d1 = s1*w1c ----
        {
            float xtv[4][2];
            const int mb = 2 * (lane & 3);
#pragma unroll
            for (int nt = 0; nt < 4; nt++) {
                xtv[nt][0] = cst[640 + nt * 8 + mb];
                xtv[nt][1] = cst[640 + nt * 8 + mb + 1];
            }
            float aV[4][4], dV[4][4];
#pragma unroll
            for (int nt = 0; nt < 4; nt++)
#pragma unroll
                for (int r = 0; r < 4; r++) {
                    const int rh = r >> 1;
                    float p = F[nt][r] + b1v[rh] + w1cv[rh] * xtv[nt][r & 1];
                    float s = (p > 0.f) ? 1.f : SLOPE;
                    aV[nt][r] = p * s;
                    dV[nt][r] = s * w1cv[rh];
                }
#pragma unroll
            for (int rh = 0; rh < 2; rh++)
                store_ad(rowAH, rowAL, rowDH, rowDL,
                         (uint32_t)((warp * 16 + rh * 8) * 2), aV, dV, rh);
        }
        __syncthreads();   // S2: A/D tiles ready

        // ======== Layer 2 ========
#pragma unroll
        for (int j = 0; j < 4; j++)
#pragma unroll
            for (int r = 0; r < 4; r++) { F[j][r] = 0.f; G[j][r] = 0.f; }
        layer_fused(w2hiA, w2loA, ahiB, aloB, dhiB, dloB, F, G);
        __syncthreads();   // S3: all warps done reading A/D

        {
            float aV[4][4], dV[4][4];
#pragma unroll
            for (int nt = 0; nt < 4; nt++)
#pragma unroll
                for (int r = 0; r < 4; r++) {
                    const int rh = r >> 1;
                    float p = F[nt][r] + b2v[rh];
                    float s = (p > 0.f) ? 1.f : SLOPE;
                    aV[nt][r] = p * s;
                    dV[nt][r] = s * G[nt][r];
                }
#pragma unroll
            for (int rh = 0; rh < 2; rh++)
                store_ad(rowAH, rowAL, rowDH, rowDL,
                         (uint32_t)((warp * 16 + rh * 8) * 2), aV, dV, rh);
        }
        __syncthreads();   // S4: A/D tiles ready for L3

        // ======== Layer 3 ========
#pragma unroll
        for (int j = 0; j < 4; j++)
#pragma unroll
            for (int r = 0; r < 4; r++) { F[j][r] = 0.f; G[j][r] = 0.f; }
        layer_fused(w3hiA, w3loA, ahiB, aloB, dhiB, dloB, F, G);

        // ---- L3 epilogue -> w4-weighted partials, shuffle reduce over h ----
        {
            float pA[4][2], pD[4][2];
#pragma unroll
            for (int nt = 0; nt < 4; nt++) { pA[nt][0] = pA[nt][1] = 0.f; pD[nt][0] = pD[nt][1] = 0.f; }
#pragma unroll
            for (int nt = 0; nt < 4; nt++)
#pragma unroll
                for (int r = 0; r < 4; r++) {
                    const int rh = r >> 1;
                    float p = F[nt][r] + b3v[rh];
                    float s = (p > 0.f) ? 1.f : SLOPE;
                    pA[nt][r & 1] += w4v[rh] * (p * s);
                    pD[nt][r & 1] += w4v[rh] * (s * G[nt][r]);
                }
#pragma unroll
            for (int nt = 0; nt < 4; nt++)
#pragma unroll
                for (int c = 0; c < 2; c++) {
                    float v = pA[nt][c];
                    v += __shfl_xor_sync(0xffffffffu, v, 4);
                    v += __shfl_xor_sync(0xffffffffu, v, 8);
                    v += __shfl_xor_sync(0xffffffffu, v, 16);
                    pA[nt][c] = v;
                    float u = pD[nt][c];
                    u += __shfl_xor_sync(0xffffffffu, u, 4);
                    u += __shfl_xor_sync(0xffffffffu, u, 8);
                    u += __shfl_xor_sync(0xffffffffu, u, 16);
                    pD[nt][c] = u;
                }
            if (lane < 4) {
#pragma unroll
                for (int nt = 0; nt < 4; nt++) {
                    red[warp * 64 + nt * 8 + 2 * lane]          = pA[nt][0];
                    red[warp * 64 + nt * 8 + 2 * lane + 1]      = pA[nt][1];
                    red[warp * 64 + 32 + nt * 8 + 2 * lane]     = pD[nt][0];
                    red[warp * 64 + 32 + nt * 8 + 2 * lane + 1] = pD[nt][1];
                }
            }
        }
        __syncthreads();   // S5: red ready

        if (tid < 32) {
            const int n = n0 + tid;
            float res = b4d;
            float dv  = 0.f;
#pragma unroll
            for (int w = 0; w < 8; w++) {
                res += red[w * 64 + tid];
                dv  += red[w * 64 + 32 + tid];
            }
            out_res[(size_t)n * 64 + d] = res;
            g_scratch[d * 4096 + n] = logf(fabsf(dv) + 1e-8f);
        }
        __syncthreads();   // S6: red consumed, safe to reuse next tile
    }
}

// deterministic sum over latents: out_logdet[n] = sum_d scratch[d][n]
__global__ void reduce_logdet_kernel(float* __restrict__ out_ld)
{
    const int n = blockIdx.x * blockDim.x + threadIdx.x;
    if (n < 4096) {
        float s = 0.f;
#pragma unroll
        for (int d = 0; d < 64; d++) s += g_scratch[d * 4096 + n];
        out_ld[n] = s;
    }
}

extern "C" void kernel_launch(void* const* d_in, const int* in_sizes, int n_in,
                              void* d_out, int out_size)
{
    const float* x  = (const float*)d_in[0];
    const float* W1 = (const float*)d_in[1];
    const float* b1 = (const float*)d_in[2];
    const float* W2 = (const float*)d_in[3];
    const float* b2 = (const float*)d_in[4];
    const float* W3 = (const float*)d_in[5];
    const float* b3 = (const float*)d_in[6];
    const float* W4 = (const float*)d_in[7];
    const float* b4 = (const float*)d_in[8];
    (void)in_sizes; (void)n_in; (void)out_size;

    float* out_res = (float*)d_out;                  // [16,256,64]
    float* out_ld  = (float*)d_out + 16 * 256 * 64;  // [16,256]

    cudaFuncSetAttribute(npt_kernel, cudaFuncAttributeMaxDynamicSharedMemorySize, SMEM_BYTES);

    npt_kernel<<<128, THREADS, SMEM_BYTES>>>(x, W1, b1, W2, b2, W3, b3, W4, b4, out_res);
    reduce_logdet_kernel<<<16, 256>>>(out_ld);
}

// round 16
// speedup vs baseline: 4.4054x; 1.1097x over previous
#include <cuda_runtime.h>
#include <cuda_fp16.h>
#include <cstdint>

#define SLOPE 0.2f
#define THREADS 256
#define GRID 148

// ---------------- SMEM byte offsets ----------------
#define SM_RED    0        // 8 warps x 2 chains x 32 m floats = 2048 B
#define SM_CONST  2048     // b1,b2,b3,w4,w1c (5x128 f32) + xt (32 f32) = 2688 B
#define SM_XHI    4736     // [32 m][64 k] fp16, pitch 144 B
#define SM_XLO    9344
#define SM_W1HI   13952    // [128 h][64 k] fp16, pitch 144 B
#define SM_W1LO   32384
#define SM_AHI    50816    // [32 m][128 k] fp16 activations hi, pitch 272 B
#define SM_ALO    59520
#define SM_DHI    68224    // derivative hi
#define SM_DLO    76928    // derivative lo
#define SM_W2HI   85632    // [128 h][128 k] fp16, pitch 272 B
#define SM_W2LO   120448
#define SM_W3HI   155264
#define SM_W3LO   190080
#define SMEM_BYTES 224896

#define PITCH_W 272
#define PITCH_X 144

// deterministic cross-d logdet partials: scratch[d][n]
__device__ float g_scratch[64 * 4096];

// ================= helpers =================
__device__ __forceinline__ uint32_t smem_to_u32(const void* p) {
    uint32_t a;
    asm("{ .reg .u64 t; cvta.to.shared.u64 t, %1; cvt.u32.u64 %0, t; }" : "=r"(a) : "l"(p));
    return a;
}
// pack two f32 -> fp16x2, first arg = LOW halfword
__device__ __forceinline__ uint32_t packh(float lo, float hi) {
    __half2 h = __floats2half2_rn(lo, hi);
    return *reinterpret_cast<uint32_t*>(&h);
}
__device__ __forceinline__ float h2f(__half h) { return __half2float(h); }

__device__ __forceinline__ void ldsm4(uint32_t a, uint32_t* r) {
    asm volatile("ldmatrix.sync.aligned.m8n8.x4.shared.b16 {%0,%1,%2,%3}, [%4];"
        : "=r"(r[0]), "=r"(r[1]), "=r"(r[2]), "=r"(r[3]) : "r"(a));
}
__device__ __forceinline__ void stsm4t(uint32_t a, uint32_t r0, uint32_t r1, uint32_t r2, uint32_t r3) {
    asm volatile("stmatrix.sync.aligned.m8n8.x4.trans.shared.b16 [%0], {%1,%2,%3,%4};"
        :: "r"(a), "r"(r0), "r"(r1), "r"(r2), "r"(r3) : "memory");
}
__device__ __forceinline__ void mma_f16(float* d, const uint32_t* a, uint32_t b0, uint32_t b1) {
    asm volatile("mma.sync.aligned.m16n8k16.row.col.f32.f16.f16.f32 "
        "{%0,%1,%2,%3}, {%4,%5,%6,%7}, {%8,%9}, {%0,%1,%2,%3};"
        : "+f"(d[0]), "+f"(d[1]), "+f"(d[2]), "+f"(d[3])
        : "r"(a[0]), "r"(a[1]), "r"(a[2]), "r"(a[3]), "r"(b0), "r"(b1));
}

// split 8 fp32 into fp16 hi/lo packed words and store 16B each
__device__ __forceinline__ void split_store8(const float* v, char* dstHi, char* dstLo) {
    uint32_t hw[4], lw[4];
#pragma unroll
    for (int i = 0; i < 4; i++) {
        float v0 = v[2 * i], v1 = v[2 * i + 1];
        __half h0 = __float2half_rn(v0), h1 = __float2half_rn(v1);
        __half2 hp = __halves2half2(h0, h1);
        hw[i] = *reinterpret_cast<uint32_t*>(&hp);
        lw[i] = packh(v0 - h2f(h0), v1 - h2f(h1));
    }
    *(uint4*)dstHi = make_uint4(hw[0], hw[1], hw[2], hw[3]);
    *(uint4*)dstLo = make_uint4(lw[0], lw[1], lw[2], lw[3]);
}

// aligned source (stride multiple of 4 floats): float4 loads
__device__ __forceinline__ void stage_row_aligned(const float* src, char* dstHi, char* dstLo, int K) {
    for (int k = 0; k < K; k += 8) {
        float v[8];
        float4 va = *(const float4*)(src + k);
        float4 vb = *(const float4*)(src + k + 4);
        v[0] = va.x; v[1] = va.y; v[2] = va.z; v[3] = va.w;
        v[4] = vb.x; v[5] = vb.y; v[6] = vb.z; v[7] = vb.w;
        split_store8(v, dstHi + k * 2, dstLo + k * 2);
    }
}

// UNALIGNED source (W1 rows: 65-float stride) -> scalar loads only
__device__ __forceinline__ void stage_row_unaligned(const float* src, char* dstHi, char* dstLo, int K) {
    for (int k = 0; k < K; k += 8) {
        float v[8];
#pragma unroll
        for (int i = 0; i < 8; i++) v[i] = src[k + i];
        split_store8(v, dstHi + k * 2, dstLo + k * 2);
    }
}

// stage all weights + consts for latent d (call from all 256 threads; caller syncs)
__device__ __forceinline__ void stage_weights(
    char* smem, float* cst, int tid, int d,
    const float* W1, const float* b1, const float* b2,
    const float* b3, const float* W4,
    const float* W2, const float* W3)
{
    if (tid < 128) {
        const int h = tid;
        const float* w1r = W1 + (size_t)(d * 128 + h) * 65;   // 65-float stride: UNALIGNED
        stage_row_unaligned(w1r, smem + SM_W1HI + h * PITCH_X, smem + SM_W1LO + h * PITCH_X, 64);
        cst[h]       = b1[d * 128 + h];
        cst[128 + h] = b2[d * 128 + h];
        cst[256 + h] = b3[d * 128 + h];
        cst[384 + h] = W4[d * 128 + h];
        cst[512 + h] = w1r[64];
    } else {
        const int h = tid - 128;
        stage_row_aligned(W2 + (size_t)(d * 128 + h) * 128,
                          smem + SM_W2HI + h * PITCH_W, smem + SM_W2LO + h * PITCH_W, 128);
        stage_row_aligned(W3 + (size_t)(d * 128 + h) * 128,
                          smem + SM_W3HI + h * PITCH_W, smem + SM_W3LO + h * PITCH_W, 128);
    }
}

// epilogue store: 16h x 32m block -> A hi/lo + D hi/lo (fp16 splits)
__device__ __forceinline__ void store_ad(
    uint32_t rAH, uint32_t rAL, uint32_t rDH, uint32_t rDL, uint32_t hc2,
    const float (&aV)[4][4], const float (&dV)[4][4], int rh)
{
    uint32_t ah[4], al[4], dh[4], dl[4];
#pragma unroll
    for (int nt = 0; nt < 4; nt++) {
        float a0 = aV[nt][rh * 2], a1 = aV[nt][rh * 2 + 1];
        __half h0 = __float2half_rn(a0), h1 = __float2half_rn(a1);
        __half2 hp = __halves2half2(h0, h1);
        ah[nt] = *reinterpret_cast<uint32_t*>(&hp);
        al[nt] = packh(a0 - h2f(h0), a1 - h2f(h1));
        float d0 = dV[nt][rh * 2], d1 = dV[nt][rh * 2 + 1];
        __half g0 = __float2half_rn(d0), g1 = __float2half_rn(d1);
        __half2 gp = __halves2half2(g0, g1);
        dh[nt] = *reinterpret_cast<uint32_t*>(&gp);
        dl[nt] = packh(d0 - h2f(g0), d1 - h2f(g1));
    }
    stsm4t(rAH + hc2, ah[0], ah[1], ah[2], ah[3]);
    stsm4t(rAL + hc2, al[0], al[1], al[2], al[3]);
    stsm4t(rDH + hc2, dh[0], dh[1], dh[2], dh[3]);
    stsm4t(rDL + hc2, dl[0], dl[1], dl[2], dl[3]);
}

// fused fwd+deriv layer: F and G both 3-term fp16 split
__device__ __forceinline__ void layer_fused(
    uint32_t wHiA, uint32_t wLoA,
    uint32_t aHiB, uint32_t aLoB, uint32_t dHiB, uint32_t dLoB,
    float (&F)[4][4], float (&G)[4][4])
{
#pragma unroll
    for (int ks = 0; ks < 8; ks++) {
        const uint32_t kb = ks * 32;
        uint32_t wh[4], wl[4];
        ldsm4(wHiA + kb, wh);
        ldsm4(wLoA + kb, wl);
        uint32_t bah[8], bal[8], bdh[8], bdl[8];
        ldsm4(aHiB + kb, bah); ldsm4(aHiB + kb + 16 * PITCH_W, bah + 4);
        ldsm4(aLoB + kb, bal); ldsm4(aLoB + kb + 16 * PITCH_W, bal + 4);
        ldsm4(dHiB + kb, bdh); ldsm4(dHiB + kb + 16 * PITCH_W, bdh + 4);
        ldsm4(dLoB + kb, bdl); ldsm4(dLoB + kb + 16 * PITCH_W, bdl + 4);
#pragma unroll
        for (int nt = 0; nt < 4; nt++) {
            mma_f16(F[nt], wh, bah[2 * nt], bah[2 * nt + 1]);
            mma_f16(F[nt], wh, bal[2 * nt], bal[2 * nt + 1]);
            mma_f16(F[nt], wl, bah[2 * nt], bah[2 * nt + 1]);
            mma_f16(G[nt], wh, bdh[2 * nt], bdh[2 * nt + 1]);
            mma_f16(G[nt], wh, bdl[2 * nt], bdl[2 * nt + 1]);
            mma_f16(G[nt], wl, bdh[2 * nt], bdh[2 * nt + 1]);
        }
    }
}

__global__ void __launch_bounds__(THREADS, 1)
npt_kernel(const float* __restrict__ x,
           const float* __restrict__ W1, const float* __restrict__ b1,
           const float* __restrict__ W2, const float* __restrict__ b2,
           const float* __restrict__ W3, const float* __restrict__ b3,
           const float* __restrict__ W4, const float* __restrict__ b4,
           float* __restrict__ out_res)
{
    extern __shared__ char smem[];
    const uint32_t sb = smem_to_u32(smem);
    float* cst = (float*)(smem + SM_CONST);
    float* red = (float*)(smem + SM_RED);
    const int tid  = threadIdx.x;
    const int warp = tid >> 5;        // 0..7; warp owns h in [warp*16, warp*16+16)
    const int lane = tid & 31;

    // persistent range of global tile-units: unit u -> d = u>>7, n0 = (u&127)*32
    const int TOTAL = 64 * 128;
    const int u0 = (int)(((long long)blockIdx.x * TOTAL) / GRID);
    const int u1 = (int)(((long long)(blockIdx.x + 1) * TOTAL) / GRID);

    // ldmatrix lane offsets
    const uint32_t aOffW = (uint32_t)(lane & 15) * PITCH_W + (uint32_t)(lane >> 4) * 16;
    const uint32_t bOffW = (uint32_t)((lane & 7) + ((lane >> 4) << 3)) * PITCH_W
                         + (uint32_t)((lane >> 3) & 1) * 16;
    const uint32_t aOffX = (uint32_t)(lane & 15) * PITCH_X + (uint32_t)(lane >> 4) * 16;
    const uint32_t bOffX = (uint32_t)((lane & 7) + ((lane >> 4) << 3)) * PITCH_X
                         + (uint32_t)((lane >> 3) & 1) * 16;

    const uint32_t w1hiA = sb + SM_W1HI + warp * 16 * PITCH_X + aOffX;
    const uint32_t w1loA = sb + SM_W1LO + warp * 16 * PITCH_X + aOffX;
    const uint32_t w2hiA = sb + SM_W2HI + warp * 16 * PITCH_W + aOffW;
    const uint32_t w2loA = sb + SM_W2LO + warp * 16 * PITCH_W + aOffW;
    const uint32_t w3hiA = sb + SM_W3HI + warp * 16 * PITCH_W + aOffW;
    const uint32_t w3loA = sb + SM_W3LO + warp * 16 * PITCH_W + aOffW;
    const uint32_t xhiB  = sb + SM_XHI + bOffX;
    const uint32_t xloB  = sb + SM_XLO + bOffX;
    const uint32_t ahiB  = sb + SM_AHI + bOffW;
    const uint32_t aloB  = sb + SM_ALO + bOffW;
    const uint32_t dhiB  = sb + SM_DHI + bOffW;
    const uint32_t dloB  = sb + SM_DLO + bOffW;
    // stmatrix destination row bases (row = m = lane)
    const uint32_t rowAH = sb + SM_AHI + lane * PITCH_W;
    const uint32_t rowAL = sb + SM_ALO + lane * PITCH_W;
    const uint32_t rowDH = sb + SM_DHI + lane * PITCH_W;
    const uint32_t rowDL = sb + SM_DLO + lane * PITCH_W;

    int dcur = -1;
    float b4d = 0.f;
    float b1v[2], b2v[2], b3v[2], w4v[2], w1cv[2];

    for (int u = u0; u < u1; u++) {
        const int d  = u >> 7;
        const int n0 = (u & 127) * 32;
        const int b  = n0 >> 8;
        const int t0 = n0 & 255;

        if (d != dcur) {
            __syncthreads();   // all prior smem reads done before weight overwrite
            stage_weights(smem, cst, tid, d, W1, b1, b2, b3, W4, W2, W3);
            b4d = b4[d];
            __syncthreads();
#pragma unroll
            for (int rh = 0; rh < 2; rh++) {
                const int hh = warp * 16 + rh * 8 + (lane >> 2);
                b1v[rh]  = cst[hh];
                b2v[rh]  = cst[128 + hh];
                b3v[rh]  = cst[256 + hh];
                w4v[rh]  = cst[384 + hh];
                w1cv[rh] = cst[512 + hh];
            }
            dcur = d;
        }

        // -------- stage x tile: [32 m][64 k] hi/lo + xt[32] (256 threads) --------
        {
            const int m = tid >> 3, kq = tid & 7;   // 32 rows x 8 threads x 8 floats
            const float* xr = x + ((size_t)(b * 257 + t0 + m)) * 64 + kq * 8;
            float v[8];
            float4 ta = *(const float4*)(xr);
            float4 tb = *(const float4*)(xr + 4);
            v[0] = ta.x; v[1] = ta.y; v[2] = ta.z; v[3] = ta.w;
            v[4] = tb.x; v[5] = tb.y; v[6] = tb.z; v[7] = tb.w;
            char* rH = smem + SM_XHI + m * PITCH_X + kq * 16;
            char* rL = smem + SM_XLO + m * PITCH_X + kq * 16;
            split_store8(v, rH, rL);
            if (tid < 32)
                cst[640 + tid] = x[((size_t)(b * 257 + t0 + tid + 1)) * 64 + d];
        }
        __syncthreads();   // S1: X + xt ready

        float F[4][4], G[4][4];
#pragma unroll
        for (int j = 0; j < 4; j++)
#pragma unroll
            for (int r = 0; r < 4; r++) F[j][r] = 0.f;

        // ======== Layer 1 mma (fwd only, K=64, 3-term fp16) ========
#pragma unroll
        for (int ks = 0; ks < 4; ks++) {
            const uint32_t kb = ks * 32;
            uint32_t wh[4], wl[4];
            ldsm4(w1hiA + kb, wh);
            ldsm4(w1loA + kb, wl);
            uint32_t bh[8], bl[8];
            ldsm4(xhiB + kb, bh); ldsm4(xhiB + kb + 16 * PITCH_X, bh + 4);
            ldsm4(xloB + kb, bl); ldsm4(xloB + kb + 16 * PITCH_X, bl + 4);
#pragma unroll
            for (int nt = 0; nt < 4; nt++) {
                mma_f16(F[nt], wh, bh[2 * nt], bh[2 * nt + 1]);
                mma_f16(F[nt], wh, bl[2 * nt], bl[2 * nt + 1]);
                mma_f16(F[nt], wl, bh[2 * nt], bh[2 * nt + 1]);
            }
        }

        // ---- L1 epilogue: rank-1 x_t term + bias + leaky; d1 = s1*w1c ----
        {
            float xtv[4][2];
            const int mb = 2 * (lane & 3);
#pragma unroll
            for (int nt = 0; nt < 4; nt++) {
                xtv[nt][0] = cst[640 + nt * 8 + mb];
                xtv[nt][1] = cst[640 + nt * 8 + mb + 1];
            }
            float aV[4][4], dV[4][4];
#pragma unroll
            for (int nt = 0; nt < 4; nt++)
#pragma unroll
                for (int r = 0; r < 4; r++) {
                    const int rh = r >> 1;
                    float p = F[nt][r] + b1v[rh] + w1cv[rh] * xtv[nt][r & 1];
                    float s = (p > 0.f) ? 1.f : SLOPE;
                    aV[nt][r] = p * s;
                    dV[nt][r] = s * w1cv[rh];
                }
#pragma unroll
            for (int rh = 0; rh < 2; rh++)
                store_ad(rowAH, rowAL, rowDH, rowDL,
                         (uint32_t)((warp * 16 + rh * 8) * 2), aV, dV, rh);
        }
        __syncthreads();   // S2: A/D tiles ready

        // ======== Layer 2 ========
#pragma unroll
        for (int j = 0; j < 4; j++)
#pragma unroll
            for (int r = 0; r < 4; r++) { F[j][r] = 0.f; G[j][r] = 0.f; }
        layer_fused(w2hiA, w2loA, ahiB, aloB, dhiB, dloB, F, G);
        __syncthreads();   // S3: all warps done reading A/D

        {
            float aV[4][4], dV[4][4];
#pragma unroll
            for (int nt = 0; nt < 4; nt++)
#pragma unroll
                for (int r = 0; r < 4; r++) {
                    const int rh = r >> 1;
                    float p = F[nt][r] + b2v[rh];
                    float s = (p > 0.f) ? 1.f : SLOPE;
                    aV[nt][r] = p * s;
                    dV[nt][r] = s * G[nt][r];
                }
#pragma unroll
            for (int rh = 0; rh < 2; rh++)
                store_ad(rowAH, rowAL, rowDH, rowDL,
                         (uint32_t)((warp * 16 + rh * 8) * 2), aV, dV, rh);
        }
        __syncthreads();   // S4: A/D tiles ready for L3

        // ======== Layer 3 ========
#pragma unroll
        for (int j = 0; j < 4; j++)
#pragma unroll
            for (int r = 0; r < 4; r++) { F[j][r] = 0.f; G[j][r] = 0.f; }
        layer_fused(w3hiA, w3loA, ahiB, aloB, dhiB, dloB, F, G);

        // ---- L3 epilogue -> w4-weighted partials, shuffle reduce over h ----
        {
            float pA[4][2], pD[4][2];
#pragma unroll
            for (int nt = 0; nt < 4; nt++) { pA[nt][0] = pA[nt][1] = 0.f; pD[nt][0] = pD[nt][1] = 0.f; }
#pragma unroll
            for (int nt = 0; nt < 4; nt++)
#pragma unroll
                for (int r = 0; r < 4; r++) {
                    const int rh = r >> 1;
                    float p = F[nt][r] + b3v[rh];
                    float s = (p > 0.f) ? 1.f : SLOPE;
                    pA[nt][r & 1] += w4v[rh] * (p * s);
                    pD[nt][r & 1] += w4v[rh] * (s * G[nt][r]);
                }
#pragma unroll
            for (int nt = 0; nt < 4; nt++)
#pragma unroll
                for (int c = 0; c < 2; c++) {
                    float v = pA[nt][c];
                    v += __shfl_xor_sync(0xffffffffu, v, 4);
                    v += __shfl_xor_sync(0xffffffffu, v, 8);
                    v += __shfl_xor_sync(0xffffffffu, v, 16);
                    pA[nt][c] = v;
                    float w = pD[nt][c];
                    w += __shfl_xor_sync(0xffffffffu, w, 4);
                    w += __shfl_xor_sync(0xffffffffu, w, 8);
                    w += __shfl_xor_sync(0xffffffffu, w, 16);
                    pD[nt][c] = w;
                }
            if (lane < 4) {
#pragma unroll
                for (int nt = 0; nt < 4; nt++) {
                    red[warp * 64 + nt * 8 + 2 * lane]          = pA[nt][0];
                    red[warp * 64 + nt * 8 + 2 * lane + 1]      = pA[nt][1];
                    red[warp * 64 + 32 + nt * 8 + 2 * lane]     = pD[nt][0];
                    red[warp * 64 + 32 + nt * 8 + 2 * lane + 1] = pD[nt][1];
                }
            }
        }
        __syncthreads();   // S5: red ready

        if (tid < 32) {
            const int n = n0 + tid;
            float res = b4d;
            float dv  = 0.f;
#pragma unroll
            for (int w = 0; w < 8; w++) {
                res += red[w * 64 + tid];
                dv  += red[w * 64 + 32 + tid];
            }
            out_res[(size_t)n * 64 + d] = res;
            g_scratch[d * 4096 + n] = logf(fabsf(dv) + 1e-8f);
        }
        __syncthreads();   // S6: red consumed, safe to reuse next unit
    }
}

// deterministic sum over latents: out_logdet[n] = sum_d scratch[d][n]
__global__ void reduce_logdet_kernel(float* __restrict__ out_ld)
{
    const int n = blockIdx.x * blockDim.x + threadIdx.x;
    if (n < 4096) {
        float s = 0.f;
#pragma unroll
        for (int d = 0; d < 64; d++) s += g_scratch[d * 4096 + n];
        out_ld[n] = s;
    }
}

extern "C" void kernel_launch(void* const* d_in, const int* in_sizes, int n_in,
                              void* d_out, int out_size)
{
    const float* x  = (const float*)d_in[0];
    const float* W1 = (const float*)d_in[1];
    const float* b1 = (const float*)d_in[2];
    const float* W2 = (const float*)d_in[3];
    const float* b2 = (const float*)d_in[4];
    const float* W3 = (const float*)d_in[5];
    const float* b3 = (const float*)d_in[6];
    const float* W4 = (const float*)d_in[7];
    const float* b4 = (const float*)d_in[8];
    (void)in_sizes; (void)n_in; (void)out_size;

    float* out_res = (float*)d_out;                  // [16,256,64]
    float* out_ld  = (float*)d_out + 16 * 256 * 64;  // [16,256]

    cudaFuncSetAttribute(npt_kernel, cudaFuncAttributeMaxDynamicSharedMemorySize, SMEM_BYTES);

    npt_kernel<<<GRID, THREADS, SMEM_BYTES>>>(x, W1, b1, W2, b2, W3, b3, W4, b4, out_res);
    reduce_logdet_kernel<<<16, 256>>>(out_ld);
}